// round 5
// baseline (speedup 1.0000x reference)
#include <cuda_runtime.h>
#include <cstdint>

// Shapes (fixed per reference setup_inputs)
#define B_  16
#define C_  256
#define OUT_PER_B (128 * 128 * 256)      // 4,194,304 = 2^22
#define IN_PER_B  (64 * 64 * 256)        // 1,048,576 = 2^20

#define CHUNK_B          2
#define NCHUNK           8
#define CHUNK_OUT_F      (CHUNK_B * OUT_PER_B)       // 8,388,608 floats
#define CHUNK_OUT_BYTES  (CHUNK_OUT_F * 4)           // 33,554,432 B
#define CHUNK_GROUPS     ((CHUNK_B * IN_PER_B) / 4)  // 524,288 groups of 4

// 580 blocks <= 4 blocks/SM * 145 SMs -> guaranteed co-resident (chip has 148+)
#define BLOCKS   580
#define THREADS  256
#define NTHREADS (BLOCKS * THREADS)

#define ZTILE_BYTES       16384
#define ZTILES_PER_CHUNK  (CHUNK_OUT_BYTES / ZTILE_BYTES)   // 2048

// Cross-block pipeline state. Protocol restores all zeros by end of each run,
// so graph replays are deterministic.
__device__ unsigned int g_cnt[NCHUNK];    // zero-done arrivals per chunk
__device__ unsigned int g_done[NCHUNK];   // barrier-passed arrivals per chunk

__device__ __forceinline__ uint32_t smem_u32(const void* p) {
    uint32_t a;
    asm("{ .reg .u64 t; cvta.to.shared.u64 t, %1; cvt.u32.u64 %0, t; }"
        : "=r"(a) : "l"(p));
    return a;
}

__device__ __forceinline__ unsigned int ld_cg(const unsigned int* p) {
    unsigned int v;
    asm volatile("ld.global.cg.u32 %0, [%1];" : "=r"(v) : "l"(p));
    return v;
}

// thread 0 only: TMA-zero this block's slice of a chunk region
__device__ __forceinline__ void tma_zero_slice(char* region, uint32_t zsrc) {
    for (int t = blockIdx.x; t < ZTILES_PER_CHUNK; t += BLOCKS) {
        char* dst = region + (size_t)t * ZTILE_BYTES;
        asm volatile("cp.async.bulk.global.shared::cta.bulk_group [%0], [%1], %2;"
                     :: "l"(dst), "r"(zsrc), "n"(ZTILE_BYTES) : "memory");
    }
    asm volatile("cp.async.bulk.commit_group;" ::: "memory");
    asm volatile("cp.async.bulk.wait_group 0;" ::: "memory");
}

__global__ void __launch_bounds__(THREADS, 4) unpool_persistent_kernel(
        const float4* __restrict__ updates4,
        const int4*   __restrict__ mask4,
        float*        __restrict__ out) {
    __shared__ __align__(128) float4 zbuf[ZTILE_BYTES / 16];

    // zero the smem source tile once
    float4 z = make_float4(0.f, 0.f, 0.f, 0.f);
#pragma unroll
    for (int j = 0; j < 4; j++)
        zbuf[threadIdx.x + j * THREADS] = z;
    __syncthreads();
    if (threadIdx.x == 0)
        asm volatile("fence.proxy.async.shared::cta;" ::: "memory");

    uint32_t zsrc = smem_u32(zbuf);
    int tid = blockIdx.x * THREADS + threadIdx.x;

    // prologue: zero chunk 0, announce
    if (threadIdx.x == 0) {
        tma_zero_slice((char*)out, zsrc);
        __threadfence();
        atomicAdd(&g_cnt[0], 1u);
    }

    for (int c = 0; c < NCHUNK; c++) {
        if (threadIdx.x == 0) {
            // zero next chunk's region (overlaps other blocks' scatter work)
            if (c + 1 < NCHUNK) {
                tma_zero_slice((char*)(out + (size_t)(c + 1) * CHUNK_OUT_F), zsrc);
                __threadfence();
                atomicAdd(&g_cnt[c + 1], 1u);
            }
            // wait until ALL blocks have zeroed chunk c
            while (ld_cg(&g_cnt[c]) < BLOCKS) __nanosleep(128);
            __threadfence();
            // passed: last passer resets state for the next graph replay
            unsigned int old = atomicAdd(&g_done[c], 1u);
            if (old == BLOCKS - 1u) {
                g_cnt[c] = 0u;
                g_done[c] = 0u;
            }
        }
        __syncthreads();

        // scatter this chunk's groups (grid-stride)
        int base = c * CHUNK_GROUPS;
        for (int g = base + tid; g < base + CHUNK_GROUPS; g += NTHREADS) {
            int4   m = mask4[g];
            float4 u = updates4[g];
            int e0 = g << 2;                               // first element index
            float* ob = out + ((size_t)(e0 >> 20) << 22)   // batch base
                            + (e0 & (C_ - 1));             // channel of lane 0
            atomicAdd(ob + (m.x & ~(C_ - 1)) + 0, u.x);
            atomicAdd(ob + (m.y & ~(C_ - 1)) + 1, u.y);
            atomicAdd(ob + (m.z & ~(C_ - 1)) + 2, u.z);
            atomicAdd(ob + (m.w & ~(C_ - 1)) + 3, u.w);
        }
    }
}

extern "C" void kernel_launch(void* const* d_in, const int* in_sizes, int n_in,
                              void* d_out, int out_size) {
    const float4* updates4 = (const float4*)d_in[0];
    const int4*   mask4    = (const int4*)d_in[1];
    float*        out      = (float*)d_out;
    unpool_persistent_kernel<<<BLOCKS, THREADS>>>(updates4, mask4, out);
}

// round 6
// speedup vs baseline: 1.0542x; 1.0542x over previous
#include <cuda_runtime.h>
#include <cstdint>

// Shapes (fixed per reference setup_inputs)
#define C_  256
#define OUT_PER_B (1 << 22)              // 128*128*256
#define IN_PER_B  (1 << 20)              // 64*64*256

#define NCHUNK           8
#define CHUNK_OUT_F      (2 * OUT_PER_B)             // 8,388,608 floats (2 batches)
#define CHUNK_OUT_BYTES  (CHUNK_OUT_F * 4)           // 33,554,432 B
#define CHUNK_GROUPS     ((2 * IN_PER_B) / 4)        // 524,288 groups of 4

#define BLOCKS   1184                    // 148 SMs * 8 CTAs
#define THREADS  256
#define NTHREADS (BLOCKS * THREADS)      // 303,104

#define ZTILE_BYTES       16384
#define ZTILES_PER_CHUNK  (CHUNK_OUT_BYTES / ZTILE_BYTES)   // 2048

__device__ __forceinline__ uint32_t smem_u32(const void* p) {
    uint32_t a;
    asm("{ .reg .u64 t; cvta.to.shared.u64 t, %1; cvt.u32.u64 %0, t; }"
        : "=r"(a) : "l"(p));
    return a;
}

// thread 0 of each block: TMA-zero this block's slice of a 33.5 MB chunk region
__device__ __forceinline__ void tma_zero_slice(char* region, uint32_t zsrc) {
    asm volatile("fence.proxy.async.shared::cta;" ::: "memory");
    for (int t = blockIdx.x; t < ZTILES_PER_CHUNK; t += BLOCKS) {
        char* dst = region + (size_t)t * ZTILE_BYTES;
        asm volatile("cp.async.bulk.global.shared::cta.bulk_group [%0], [%1], %2;"
                     :: "l"(dst), "r"(zsrc), "n"(ZTILE_BYTES) : "memory");
    }
    asm volatile("cp.async.bulk.commit_group;" ::: "memory");
    asm volatile("cp.async.bulk.wait_group 0;" ::: "memory");
    asm volatile("membar.gl;" ::: "memory");
}

// Prime: zero chunk 0, then signal dependents (kernel for chunk 0 may start).
__global__ void __launch_bounds__(THREADS) prime_zero_kernel(float* __restrict__ out) {
    __shared__ __align__(128) float4 zbuf[ZTILE_BYTES / 16];
    float4 z = make_float4(0.f, 0.f, 0.f, 0.f);
#pragma unroll
    for (int j = 0; j < 4; j++)
        zbuf[threadIdx.x + j * THREADS] = z;
    __syncthreads();
    if (threadIdx.x == 0)
        tma_zero_slice((char*)out, smem_u32(zbuf));
    __syncthreads();
    asm volatile("griddepcontrol.launch_dependents;" ::: "memory");
}

// Chunk-c kernel (PDL secondary):
//   pre-phase : load chunk c's inputs (no hazard), zero smem TMA source
//   zero      : TMA-zero chunk c+1's region, complete + fence
//   signal    : launch_dependents  (successor only needs OUR zero of c+1)
//   wait      : griddepcontrol.wait (predecessor's zero of chunk c visible)
//   scatter   : RED.ADD stream into chunk c (drain overlaps successor's pre-phase)
__global__ void __launch_bounds__(THREADS) fused_scatter_kernel(
        const float4* __restrict__ updates4,
        const int4*   __restrict__ mask4,
        float*        __restrict__ out,
        int chunk) {
    __shared__ __align__(128) float4 zbuf[ZTILE_BYTES / 16];

    int tid = blockIdx.x * blockDim.x + threadIdx.x;

    // ---- pre-phase: input loads (pure reads of const inputs) ----
    int g0 = chunk * CHUNK_GROUPS + tid;
    int g1 = g0 + NTHREADS;
    bool has1 = (tid + NTHREADS) < CHUNK_GROUPS;

    int4   ma = mask4[g0];
    float4 ua = updates4[g0];
    int4   mb;
    float4 ub;
    if (has1) { mb = mask4[g1]; ub = updates4[g1]; }

    // smem TMA source tile
    float4 z = make_float4(0.f, 0.f, 0.f, 0.f);
#pragma unroll
    for (int j = 0; j < 4; j++)
        zbuf[threadIdx.x + j * THREADS] = z;
    __syncthreads();

    // ---- zero chunk c+1 (hazard-free vs predecessor) ----
    if (chunk + 1 < NCHUNK && threadIdx.x == 0)
        tma_zero_slice((char*)(out + (size_t)(chunk + 1) * CHUNK_OUT_F),
                       smem_u32(zbuf));
    __syncthreads();

    // our zero is complete -> successor may begin
    asm volatile("griddepcontrol.launch_dependents;" ::: "memory");
    // predecessor's zero of chunk c must be visible before our atomics
    asm volatile("griddepcontrol.wait;" ::: "memory");

    // ---- scatter chunk c: dest = out + b*OUT_PER_B + (mask & ~(C-1)) + channel ----
    int e0a = g0 << 2;
    float* oa = out + ((size_t)(e0a >> 20) << 22) + (e0a & (C_ - 1));
    atomicAdd(oa + (ma.x & ~(C_ - 1)) + 0, ua.x);
    atomicAdd(oa + (ma.y & ~(C_ - 1)) + 1, ua.y);
    atomicAdd(oa + (ma.z & ~(C_ - 1)) + 2, ua.z);
    atomicAdd(oa + (ma.w & ~(C_ - 1)) + 3, ua.w);
    if (has1) {
        int e0b = g1 << 2;
        float* ob = out + ((size_t)(e0b >> 20) << 22) + (e0b & (C_ - 1));
        atomicAdd(ob + (mb.x & ~(C_ - 1)) + 0, ub.x);
        atomicAdd(ob + (mb.y & ~(C_ - 1)) + 1, ub.y);
        atomicAdd(ob + (mb.z & ~(C_ - 1)) + 2, ub.z);
        atomicAdd(ob + (mb.w & ~(C_ - 1)) + 3, ub.w);
    }
}

extern "C" void kernel_launch(void* const* d_in, const int* in_sizes, int n_in,
                              void* d_out, int out_size) {
    const float4* updates4 = (const float4*)d_in[0];
    const int4*   mask4    = (const int4*)d_in[1];
    float*        out      = (float*)d_out;

    // Prime: zero chunk 0 (plain launch; first fused kernel overlaps via PDL)
    prime_zero_kernel<<<BLOCKS, THREADS>>>(out);

    // Chain of PDL-overlapped chunk kernels
    cudaLaunchAttribute attr[1];
    attr[0].id = cudaLaunchAttributeProgrammaticStreamSerialization;
    attr[0].val.programmaticStreamSerializationAllowed = 1;

    cudaLaunchConfig_t cfg = {};
    cfg.gridDim = dim3(BLOCKS, 1, 1);
    cfg.blockDim = dim3(THREADS, 1, 1);
    cfg.dynamicSmemBytes = 0;
    cfg.stream = 0;                       // legacy default stream (capture target)
    cfg.attrs = attr;
    cfg.numAttrs = 1;

    for (int c = 0; c < NCHUNK; c++) {
        cudaLaunchKernelEx(&cfg, fused_scatter_kernel, updates4, mask4, out, c);
    }
}

// round 7
// speedup vs baseline: 1.1867x; 1.1257x over previous
#include <cuda_runtime.h>
#include <cstdint>

// Shapes (fixed per reference setup_inputs)
#define C_  256
#define OUT_PER_B (1 << 22)              // 128*128*256
#define IN_PER_B  (1 << 20)              // 64*64*256

#define NCHUNK           8
#define CHUNK_OUT_F      (2 * OUT_PER_B)             // 8,388,608 floats (2 batches)
#define CHUNK_OUT_F4     (CHUNK_OUT_F / 4)           // 2,097,152 float4
#define CHUNK_GROUPS     ((2 * IN_PER_B) / 4)        // 524,288 groups of 4

// scatter grid: exact 2 groups per thread
#define SBLOCKS   1024
#define STHREADS  256
#define SNTHREADS (SBLOCKS * STHREADS)               // 262,144

// zero grid: small, DRAM-bound, runs beside scatter
#define ZBLOCKS   256
#define ZTHREADS  256
#define ZNTHREADS (ZBLOCKS * ZTHREADS)               // 65,536
#define ZITERS    (CHUNK_OUT_F4 / ZNTHREADS)         // 32

__global__ void __launch_bounds__(ZTHREADS) zero_chunk_kernel(float4* __restrict__ dst) {
    int tid = blockIdx.x * ZTHREADS + threadIdx.x;
    float4 z = make_float4(0.f, 0.f, 0.f, 0.f);
#pragma unroll
    for (int j = 0; j < ZITERS; j++)
        dst[tid + j * ZNTHREADS] = z;
}

// Pure scatter: 2 independent groups (8 elements, 8 REDs) per thread.
__global__ void __launch_bounds__(STHREADS) scatter_chunk_kernel(
        const float4* __restrict__ updates4,
        const int4*   __restrict__ mask4,
        float*        __restrict__ out,
        int chunk) {
    int tid = blockIdx.x * STHREADS + threadIdx.x;
    int g0 = chunk * CHUNK_GROUPS + tid;
    int g1 = g0 + SNTHREADS;

    int4   ma = mask4[g0];
    float4 ua = updates4[g0];
    int4   mb = mask4[g1];
    float4 ub = updates4[g1];

    // dest = out + b*OUT_PER_B + (mask & ~(C-1)) + channel(lane)
    int e0a = g0 << 2;
    int e0b = g1 << 2;
    float* oa = out + ((size_t)(e0a >> 20) << 22) + (e0a & (C_ - 1));
    float* ob = out + ((size_t)(e0b >> 20) << 22) + (e0b & (C_ - 1));

    atomicAdd(oa + (ma.x & ~(C_ - 1)) + 0, ua.x);
    atomicAdd(oa + (ma.y & ~(C_ - 1)) + 1, ua.y);
    atomicAdd(oa + (ma.z & ~(C_ - 1)) + 2, ua.z);
    atomicAdd(oa + (ma.w & ~(C_ - 1)) + 3, ua.w);
    atomicAdd(ob + (mb.x & ~(C_ - 1)) + 0, ub.x);
    atomicAdd(ob + (mb.y & ~(C_ - 1)) + 1, ub.y);
    atomicAdd(ob + (mb.z & ~(C_ - 1)) + 2, ub.z);
    atomicAdd(ob + (mb.w & ~(C_ - 1)) + 3, ub.w);
}

extern "C" void kernel_launch(void* const* d_in, const int* in_sizes, int n_in,
                              void* d_out, int out_size) {
    const float4* updates4 = (const float4*)d_in[0];
    const int4*   mask4    = (const int4*)d_in[1];
    float*        out      = (float*)d_out;

    // One-time host resources (handles only; no device memory).
    static cudaStream_t zs = nullptr;
    static cudaEvent_t  evFork = nullptr;
    static cudaEvent_t  evZero[NCHUNK];
    if (zs == nullptr) {
        cudaStreamCreateWithFlags(&zs, cudaStreamNonBlocking);
        cudaEventCreateWithFlags(&evFork, cudaEventDisableTiming);
        for (int c = 0; c < NCHUNK; c++)
            cudaEventCreateWithFlags(&evZero[c], cudaEventDisableTiming);
    }

    // Fork: zero chain on side stream zs, scatter chain on stream 0.
    cudaEventRecord(evFork, 0);
    cudaStreamWaitEvent(zs, evFork, 0);

    for (int c = 0; c < NCHUNK; c++) {
        float4* region = (float4*)(out + (size_t)c * CHUNK_OUT_F);
        zero_chunk_kernel<<<ZBLOCKS, ZTHREADS, 0, zs>>>(region);
        cudaEventRecord(evZero[c], zs);
    }

    for (int c = 0; c < NCHUNK; c++) {
        cudaStreamWaitEvent(0, evZero[c], 0);   // scatter(c) needs zero(c)
        scatter_chunk_kernel<<<SBLOCKS, STHREADS, 0, 0>>>(updates4, mask4, out, c);
    }
    // The last scatter's wait on evZero[7] also joins zs back into stream 0,
    // so the capture graph is fully joined at the end of kernel_launch.
}